// round 14
// baseline (speedup 1.0000x reference)
#include <cuda_runtime.h>

// Problem constants
#define B_   16
#define NQ_  2048
#define NK_  2048
#define D_   128
#define BM   64      // q rows per CTA
#define BN   64      // keys per k-tile
#define QP   132     // smem pitch (floats) for Q/K/V tiles: 132%32=4 -> conflict-free LDS.128 with 16-strided cols
#define PP   80      // smem pitch for P tile: 80%32=16 -> conflict-free P stores
#define NSEG 4
#define SEGLEN (NK_ / NSEG)

// Per-batch masked-V partial suffix sums (scratch; __device__ global per allocation rules)
__device__ float g_mvs[NSEG * B_ * D_];

// ---------------------------------------------------------------------------
// valid_lens dtype-robust load.
// Reference declares jnp.int64, but JAX default config (x64 disabled) silently
// produces int32 — the harness dtype legend lists int32 only. Sniff which one:
// read the first 16 int32 words (in-bounds for BOTH layouts: int32[16]=64B,
// int64[16]=128B). If every odd word is zero, it's little-endian int64 high
// words (genuine int32 data has 8 random lengths all-zero with prob ~2^-88);
// then w[2b] (in-bounds, buffer is 128B). Otherwise int32: w[b].
// ---------------------------------------------------------------------------
__device__ __forceinline__ int load_L(const void* vlp, int b) {
    const int* w = (const int*)vlp;
    bool i64 = true;
#pragma unroll
    for (int i = 1; i < 16; i += 2) i64 &= (w[i] == 0);
    int L = i64 ? w[2 * b] : w[b];
    return min(max(L, 0), NK_);
}

// ---------------------------------------------------------------------------
// Kernel A: masked V suffix sums.
// g_mvs[s][b][d] = sum_{k in [s*512,(s+1)*512) ∩ [L,2048)} V[b,k,d]
// ---------------------------------------------------------------------------
__global__ void mvs_kernel(const float* __restrict__ V, const void* __restrict__ vl) {
    int b = blockIdx.x, s = blockIdx.y, d = threadIdx.x;
    int L = load_L(vl, b);
    int k1 = (s + 1) * SEGLEN;
    int k  = max(L, s * SEGLEN);
    const float* vb = V + (size_t)b * NK_ * D_;
    float s0 = 0.f, s1 = 0.f, s2 = 0.f, s3 = 0.f;
    for (; k + 4 <= k1; k += 4) {
        s0 += vb[(k + 0) * D_ + d];
        s1 += vb[(k + 1) * D_ + d];
        s2 += vb[(k + 2) * D_ + d];
        s3 += vb[(k + 3) * D_ + d];
    }
    for (; k < k1; k++) s0 += vb[k * D_ + d];
    g_mvs[(s * B_ + b) * D_ + d] = (s0 + s1) + (s2 + s3);
}

// ---------------------------------------------------------------------------
// Kernel B: flash attention over k < L, online softmax seeded with the masked
// contribution (masked score == 1e-8 exactly; weight 1 at m0 = 1e-8,
// l0 = Nk - L, acc0 = sum of masked V). Exactly reproduces reference softmax.
//
// Thread org: 256 threads as 16x16 (ty, tx).
//   S tile rows owned:  r_i = ty + 16*i, i in 0..3
//   S tile cols owned:  c_j = tx + 16*j, j in 0..3
//   O cols owned:       tx + 16*j, j in 0..7
// ---------------------------------------------------------------------------
__global__ __launch_bounds__(256, 1)
void attn_kernel(const float* __restrict__ Q, const float* __restrict__ K,
                 const float* __restrict__ V, const void* __restrict__ vl,
                 float* __restrict__ O) {
    extern __shared__ float sm[];
    float* sQ = sm;                    // BM x QP
    float* sK = sQ + BM * QP;          // BN x QP
    float* sV = sK + BN * QP;          // BN x QP
    float* sP = sV + BN * QP;          // BM x PP

    const int b   = blockIdx.y;
    const int q0  = blockIdx.x * BM;
    const int tid = threadIdx.x;
    const int ty  = tid >> 4;
    const int tx  = tid & 15;

    const int L = load_L(vl, b);

    const float* Qb = Q + ((size_t)b * NQ_ + q0) * D_;
    const float* Kb = K + (size_t)b * NK_ * D_;
    const float* Vb = V + (size_t)b * NK_ * D_;

    // ---- load Q tile (64 x 128 fp32), float4 coalesced ----
#pragma unroll
    for (int it = 0; it < (BM * D_ / 4) / 256; it++) {
        int idx = tid + it * 256;
        int row = idx >> 5;      // 32 float4 per row
        int c4  = idx & 31;
        float4 v = *(const float4*)(Qb + row * D_ + c4 * 4);
        *(float4*)(sQ + row * QP + c4 * 4) = v;
    }

    // ---- init accumulators with the masked-positions contribution ----
    float acc[4][8];
#pragma unroll
    for (int j = 0; j < 8; j++) {
        float s = 0.f;
#pragma unroll
        for (int sg = 0; sg < NSEG; sg++) s += g_mvs[(sg * B_ + b) * D_ + tx + 16 * j];
#pragma unroll
        for (int i = 0; i < 4; i++) acc[i][j] = s;
    }
    float mrow[4], lrow[4];
    const float linit = (float)(NK_ - L);
#pragma unroll
    for (int i = 0; i < 4; i++) { mrow[i] = 1e-8f; lrow[i] = linit; }

    const int nTiles = (L + BN - 1) / BN;
    const float scale = 0.08838834764831845f;  // 1/sqrt(128)

    for (int kt = 0; kt < nTiles; kt++) {
        // ---- load K,V tiles ----
        const float* Kt = Kb + (size_t)kt * BN * D_;
        const float* Vt = Vb + (size_t)kt * BN * D_;
#pragma unroll
        for (int it = 0; it < (BN * D_ / 4) / 256; it++) {
            int idx = tid + it * 256;
            int row = idx >> 5;
            int c4  = idx & 31;
            float4 kv = *(const float4*)(Kt + row * D_ + c4 * 4);
            float4 vv = *(const float4*)(Vt + row * D_ + c4 * 4);
            *(float4*)(sK + row * QP + c4 * 4) = kv;
            *(float4*)(sV + row * QP + c4 * 4) = vv;
        }
        __syncthreads();

        // ---- GEMM1: S = Q K^T  (4x4 per thread) ----
        float s[4][4];
#pragma unroll
        for (int i = 0; i < 4; i++)
#pragma unroll
            for (int j = 0; j < 4; j++) s[i][j] = 0.f;

#pragma unroll 2
        for (int kk = 0; kk < D_; kk += 4) {
            float4 qf[4], kf[4];
#pragma unroll
            for (int i = 0; i < 4; i++) qf[i] = *(const float4*)(sQ + (ty + 16 * i) * QP + kk);
#pragma unroll
            for (int j = 0; j < 4; j++) kf[j] = *(const float4*)(sK + (tx + 16 * j) * QP + kk);
#pragma unroll
            for (int i = 0; i < 4; i++)
#pragma unroll
                for (int j = 0; j < 4; j++) {
                    s[i][j] += qf[i].x * kf[j].x;
                    s[i][j] += qf[i].y * kf[j].y;
                    s[i][j] += qf[i].z * kf[j].z;
                    s[i][j] += qf[i].w * kf[j].w;
                }
        }

        // ---- masking + online softmax ----
        const int kbase = kt * BN;
        const bool fullvalid = (kbase + BN) <= L;
#pragma unroll
        for (int i = 0; i < 4; i++) {
            float tm = -1e30f;
#pragma unroll
            for (int j = 0; j < 4; j++) {
                float sv = s[i][j] * scale;
                if (!fullvalid && (kbase + tx + 16 * j) >= L) sv = -1e30f;  // excluded (handled by seed)
                s[i][j] = sv;
                tm = fmaxf(tm, sv);
            }
#pragma unroll
            for (int off = 8; off; off >>= 1)
                tm = fmaxf(tm, __shfl_xor_sync(0xffffffffu, tm, off));
            float mnew = fmaxf(mrow[i], tm);
            float r = __expf(mrow[i] - mnew);
            float ps = 0.f;
            float p[4];
#pragma unroll
            for (int j = 0; j < 4; j++) {
                p[j] = __expf(s[i][j] - mnew);   // masked -> exp(-huge) == 0
                ps += p[j];
            }
#pragma unroll
            for (int off = 8; off; off >>= 1)
                ps += __shfl_xor_sync(0xffffffffu, ps, off);
            lrow[i] = lrow[i] * r + ps;
            mrow[i] = mnew;
#pragma unroll
            for (int j = 0; j < 8; j++) acc[i][j] *= r;
#pragma unroll
            for (int j = 0; j < 4; j++)
                sP[(ty + 16 * i) * PP + tx + 16 * j] = p[j];
        }
        __syncthreads();

        // ---- GEMM2: acc += P V  (4x8 per thread) ----
#pragma unroll 2
        for (int kk = 0; kk < BN; kk++) {
            float pv[4], vv[8];
#pragma unroll
            for (int i = 0; i < 4; i++) pv[i] = sP[(ty + 16 * i) * PP + kk];
#pragma unroll
            for (int j = 0; j < 8; j++) vv[j] = sV[kk * QP + tx + 16 * j];
#pragma unroll
            for (int i = 0; i < 4; i++)
#pragma unroll
                for (int j = 0; j < 8; j++) acc[i][j] += pv[i] * vv[j];
        }
        __syncthreads();  // protect sK/sV/sP before next tile's loads
    }

    // ---- epilogue: normalize and store ----
    float* Ob = O + ((size_t)b * NQ_ + q0) * D_;
#pragma unroll
    for (int i = 0; i < 4; i++) {
        float inv = 1.0f / lrow[i];   // lrow >= 1 always (L <= 2047 -> linit >= 1)
#pragma unroll
        for (int j = 0; j < 8; j++)
            Ob[(ty + 16 * i) * D_ + tx + 16 * j] = acc[i][j] * inv;
    }
}

// ---------------------------------------------------------------------------
extern "C" void kernel_launch(void* const* d_in, const int* in_sizes, int n_in,
                              void* d_out, int out_size) {
    const float* Q = (const float*)d_in[0];
    const float* K = (const float*)d_in[1];
    const float* V = (const float*)d_in[2];
    const void*  vl = d_in[3];
    float* O = (float*)d_out;

    mvs_kernel<<<dim3(B_, NSEG), D_>>>(V, vl);

    size_t smem = (size_t)(3 * BM * QP + BM * PP) * sizeof(float);
    cudaFuncSetAttribute(attn_kernel, cudaFuncAttributeMaxDynamicSharedMemorySize, (int)smem);
    attn_kernel<<<dim3(NQ_ / BM, B_), 256, smem>>>(Q, K, V, vl, O);
}